// round 13
// baseline (speedup 1.0000x reference)
#include <cuda_runtime.h>
#include <cuda_fp16.h>
#include <math.h>
#include <stdint.h>

#define BB   2048
#define NSEQ 20
#define DD   512
#define HH   8
#define DKH  64
#define DQF  64
#define MTOT (BB*NSEQ)     /* 40960 */
#define KC   (3*DD)        /* 1536  */

// ---------------- scratch (no allocations allowed) ----------------
__device__ __half g_Xh [MTOT*DD];     // x in fp16
__device__ __half g_Wbh[3][DD*KC];    // conv B, [p][n*KC + k], k = tap*512+i
__device__ __half g_Wobh[DD*DD];      // out B, [n*DD + k]
__device__ __half g_Wqfh[DQF*DD];     // qf B, [n*DD + k]
__device__ __half g_Yh[3][MTOT*DD];   // conv out (fp16, pre-LN)
__device__ float  g_P [MTOT*HH];      // p[b,n,h]
__device__ __half g_AOh[MTOT*DD];     // attention output (fp16 for out GEMM)

// ---------------- asm helpers ----------------
__device__ __forceinline__ uint32_t s2u(const void* p) {
    uint32_t a;
    asm("{ .reg .u64 t; cvta.to.shared.u64 t, %1; cvt.u32.u64 %0, t; }" : "=r"(a) : "l"(p));
    return a;
}
#define CP_ASYNC16(s, g, sz) \
    asm volatile("cp.async.cg.shared.global [%0], [%1], 16, %2;" :: "r"(s), "l"(g), "r"(sz))
#define CP_COMMIT() asm volatile("cp.async.commit_group;" ::: "memory")
#define CP_WAIT(n)  asm volatile("cp.async.wait_group %0;" :: "n"(n) : "memory")

__device__ __forceinline__ void ldsm4(uint32_t& r0, uint32_t& r1, uint32_t& r2, uint32_t& r3,
                                      uint32_t addr) {
    asm volatile("ldmatrix.sync.aligned.m8n8.x4.shared.b16 {%0,%1,%2,%3}, [%4];"
                 : "=r"(r0), "=r"(r1), "=r"(r2), "=r"(r3) : "r"(addr));
}
__device__ __forceinline__ void mma_fp16(float* c, const uint32_t* a, const uint32_t* b) {
    asm volatile(
        "mma.sync.aligned.m16n8k16.row.col.f32.f16.f16.f32 "
        "{%0,%1,%2,%3},{%4,%5,%6,%7},{%8,%9},{%0,%1,%2,%3};"
        : "+f"(c[0]), "+f"(c[1]), "+f"(c[2]), "+f"(c[3])
        : "r"(a[0]), "r"(a[1]), "r"(a[2]), "r"(a[3]), "r"(b[0]), "r"(b[1]));
}

// smem tile geometry: rows of 32 halves (64B data) padded to 80B stride
#define SROWB  80
#define TILEB  (128*SROWB)      /* 10240 B per operand tile */
#define STAGEB (2*TILEB)        /* A + B per stage */
#define NSTAGE 3
#define SMEM_DYN (NSTAGE*STAGEB)

// qfp_tc geometry
#define QATILE 10240
#define QSTAGE 15360
#define QARENA (3*QSTAGE)

// lnattn arena
#define LA_SC  62400            /* after qkv: 3*20*520*2 */
#define LA_PV  75200            /* after scA: 8*20*20*4 */
#define LA_TOT 76032

// ---------------- prep kernels ----------------
__global__ void k_prepXh(const float* __restrict__ x) {
    int t = blockIdx.x * 256 + threadIdx.x;
    float4 v = *(const float4*)(x + (size_t)t * 4);
    __half2 h0 = __floats2half2_rn(v.x, v.y);
    __half2 h1 = __floats2half2_rn(v.z, v.w);
    *(uint32_t*)(&g_Xh[(size_t)t*4])     = *(uint32_t*)&h0;
    *(uint32_t*)(&g_Xh[(size_t)t*4 + 2]) = *(uint32_t*)&h1;
}
__global__ void k_prepB(const float* __restrict__ Wq,
                        const float* __restrict__ Wk,
                        const float* __restrict__ Wv) {
    const float* W = (blockIdx.z == 0) ? Wq : (blockIdx.z == 1) ? Wk : Wv;
    int k = blockIdx.x * 256 + threadIdx.x;
    int n = blockIdx.y;
    int tap = k >> 9, i = k & 511;
    g_Wbh[blockIdx.z][(size_t)n * KC + k] = __float2half_rn(W[(size_t)n * KC + i * 3 + tap]);
}
__global__ void k_prepO(const float* __restrict__ Wo) {
    int t = blockIdx.x * 256 + threadIdx.x;
    int k = t & 511, n = t >> 9;
    g_Wobh[(size_t)n * DD + k] = __float2half_rn(Wo[(size_t)k * DD + n]);
}
__global__ void k_prepQf(const float* __restrict__ Wqf) {
    int t = blockIdx.x * 256 + threadIdx.x;
    int n = t >> 9, k = t & 511;
    g_Wqfh[(size_t)n * DD + k] = __float2half_rn(Wqf[(size_t)k * DQF + n]);
}

// ---------------- qf/p via tensor cores ----------------
__global__ __launch_bounds__(256) void k_qfp_tc(const float* __restrict__ bqf,
                                                const float* __restrict__ Wqp) {
    __shared__ __align__(16) char arena[QARENA];
    uint32_t sbase = s2u(arena);
    int tid = threadIdx.x;
    int lane = tid & 31, wid = tid >> 5;
    int wm = wid & 3, wn = wid >> 2;
    int m0 = blockIdx.x * 128;

    int lr = tid >> 1, lh = tid & 1;
    const __half* aRowPtr = g_Xh + (size_t)(m0 + lr) * DD;
    uint32_t sArow = sbase + lr * SROWB + lh * 32;
    int br = (tid & 127) >> 1;
    const __half* bRowPtr = g_Wqfh + (size_t)br * DD;
    uint32_t sBrow = sbase + QATILE + br * SROWB + lh * 32;

    uint32_t aAddr = sbase + (wm*32 + (lane & 15)) * SROWB + (lane >> 4) * 16;
    uint32_t bAddr = sbase + QATILE
                   + (wn*32 + (lane & 7) + ((lane & 16) >> 1)) * SROWB
                   + ((lane >> 3) & 1) * 16;

    float acc[2][4][4] = {};
    const int NT = 16;
    #pragma unroll
    for (int t = 0; t < 2; t++) {
        uint32_t so = (uint32_t)(t * QSTAGE);
        const __half* ga = aRowPtr + t*32;
        CP_ASYNC16(sArow + so,      ga + lh*16,     16);
        CP_ASYNC16(sArow + so + 16, ga + lh*16 + 8, 16);
        if (tid < 128) {
            const __half* gb = bRowPtr + t*32;
            CP_ASYNC16(sBrow + so,      gb + lh*16,     16);
            CP_ASYNC16(sBrow + so + 16, gb + lh*16 + 8, 16);
        }
        CP_COMMIT();
    }
    int ks0 = wid & 1;
    #pragma unroll 1
    for (int t = 0; t < NT; t++) {
        if (t + 1 < NT) { CP_WAIT(1); } else { CP_WAIT(0); }
        __syncthreads();
        uint32_t so = (uint32_t)((t % 3) * QSTAGE);
        #pragma unroll
        for (int kk = 0; kk < 2; kk++) {
            int ks = ks0 ^ kk;
            uint32_t a[2][4], b[4][2];
            #pragma unroll
            for (int mt = 0; mt < 2; mt++)
                ldsm4(a[mt][0], a[mt][1], a[mt][2], a[mt][3],
                      aAddr + so + mt*16*SROWB + 32*ks);
            ldsm4(b[0][0], b[0][1], b[1][0], b[1][1], bAddr + so + 32*ks);
            ldsm4(b[2][0], b[2][1], b[3][0], b[3][1], bAddr + so + 16*SROWB + 32*ks);
            #pragma unroll
            for (int mt = 0; mt < 2; mt++)
                #pragma unroll
                for (int nt = 0; nt < 4; nt++)
                    mma_fp16(acc[mt][nt], a[mt], b[nt]);
        }
        if (t + 2 < NT) {
            int tn = t + 2;
            uint32_t sn = (uint32_t)((tn % 3) * QSTAGE);
            const __half* ga = aRowPtr + tn*32;
            CP_ASYNC16(sArow + sn,      ga + lh*16,     16);
            CP_ASYNC16(sArow + sn + 16, ga + lh*16 + 8, 16);
            if (tid < 128) {
                const __half* gb = bRowPtr + tn*32;
                CP_ASYNC16(sBrow + sn,      gb + lh*16,     16);
                CP_ASYNC16(sBrow + sn + 16, gb + lh*16 + 8, 16);
            }
            CP_COMMIT();
        }
    }
    __syncthreads();
    float* qfS = (float*)arena;               // [128][68]
    float* ws  = (float*)arena + 128*68;      // [64*8]
    #pragma unroll
    for (int mt = 0; mt < 2; mt++) {
        int r = wm*32 + mt*16 + (lane >> 2);
        #pragma unroll
        for (int nt = 0; nt < 4; nt++) {
            int c = wn*32 + nt*8 + (lane & 3)*2;
            float b0 = bqf[c], b1 = bqf[c+1];
            qfS[r*68 + c]       = tanhf(acc[mt][nt][0] + b0);
            qfS[r*68 + c + 1]   = tanhf(acc[mt][nt][1] + b1);
            qfS[(r+8)*68 + c]   = tanhf(acc[mt][nt][2] + b0);
            qfS[(r+8)*68 + c+1] = tanhf(acc[mt][nt][3] + b1);
        }
    }
    ws[tid]       = Wqp[tid];
    ws[tid + 256] = Wqp[tid + 256];
    __syncthreads();
    #pragma unroll
    for (int e = 0; e < 4; e++) {
        int idx = tid + e * 256;
        int r = idx >> 3, h = idx & 7;
        float s = 0.f;
        #pragma unroll 16
        for (int dq = 0; dq < DQF; dq++) s += qfS[r*68 + dq] * ws[dq*HH + h];
        g_P[(size_t)(m0 + r) * HH + h] = s;
    }
}

// ---------------- conv QKV GEMM (fp16 mma.sync, 3-stage, ks-staggered) ----------------
__global__ __launch_bounds__(256) void k_conv_h(int dummy) {
    extern __shared__ __half smh[];
    uint32_t sbase = s2u(smh);
    int tid = threadIdx.x;
    int lane = tid & 31, wid = tid >> 5;
    int wm = wid & 1, wn = wid >> 1;
    int n0 = blockIdx.x * 128, m0 = blockIdx.y * 128, p = blockIdx.z;
    const __half* Wb = g_Wbh[p];
    __half* Y = g_Yh[p];

    int lr = tid >> 1, lh = tid & 1;
    int nrowA = (m0 + lr) % NSEQ;
    const __half* aRowPtr = g_Xh + (size_t)(m0 + lr) * DD;
    const __half* bRowPtr = Wb + (size_t)(n0 + lr) * KC;
    uint32_t sArow = sbase + lr * SROWB + lh * 32;
    uint32_t sBrow = sbase + TILEB + lr * SROWB + lh * 32;

    int aRow = wm*64 + (lane & 15);
    int aU   = lane >> 4;
    int bRow = wn*32 + (lane & 7) + ((lane & 16) >> 1);
    int bU   = (lane >> 3) & 1;
    uint32_t aAddr = sbase + aRow * SROWB + aU * 16;
    uint32_t bAddr = sbase + TILEB + bRow * SROWB + bU * 16;

    float acc[4][4][4] = {};
    const int NT = 48;

    #pragma unroll
    for (int t = 0; t < 2; t++) {
        int tap = t >> 4, ib = (t & 15) * 32;
        uint32_t so = (uint32_t)(t * STAGEB);
        int ok = ((unsigned)(nrowA + tap - 1) < (unsigned)NSEQ) ? 16 : 0;
        const __half* ga = ok ? (aRowPtr + (ptrdiff_t)(tap-1)*DD + ib) : g_Xh;
        const __half* gb = bRowPtr + t*32;
        CP_ASYNC16(sArow + so,      ga + lh*16,     ok);
        CP_ASYNC16(sArow + so + 16, ga + lh*16 + 8, ok);
        CP_ASYNC16(sBrow + so,      gb + lh*16,     16);
        CP_ASYNC16(sBrow + so + 16, gb + lh*16 + 8, 16);
        CP_COMMIT();
    }
    int ks0 = wid & 1;
    #pragma unroll 1
    for (int t = 0; t < NT; t++) {
        if (t + 1 < NT) { CP_WAIT(1); } else { CP_WAIT(0); }
        __syncthreads();
        uint32_t so = (uint32_t)((t % NSTAGE) * STAGEB);
        #pragma unroll
        for (int kk = 0; kk < 2; kk++) {
            int ks = ks0 ^ kk;
            uint32_t a[4][4], b[4][2];
            #pragma unroll
            for (int mt = 0; mt < 4; mt++)
                ldsm4(a[mt][0], a[mt][1], a[mt][2], a[mt][3],
                      aAddr + so + mt*16*SROWB + 32*ks);
            #pragma unroll
            for (int ntp = 0; ntp < 2; ntp++)
                ldsm4(b[2*ntp][0], b[2*ntp][1], b[2*ntp+1][0], b[2*ntp+1][1],
                      bAddr + so + ntp*16*SROWB + 32*ks);
            #pragma unroll
            for (int mt = 0; mt < 4; mt++)
                #pragma unroll
                for (int nt = 0; nt < 4; nt++)
                    mma_fp16(acc[mt][nt], a[mt], b[nt]);
        }
        if (t + 2 < NT) {
            int tn = t + 2, tap = tn >> 4, ib = (tn & 15) * 32;
            uint32_t sn = (uint32_t)((tn % NSTAGE) * STAGEB);
            int ok = ((unsigned)(nrowA + tap - 1) < (unsigned)NSEQ) ? 16 : 0;
            const __half* ga = ok ? (aRowPtr + (ptrdiff_t)(tap-1)*DD + ib) : g_Xh;
            const __half* gb = bRowPtr + tn*32;
            CP_ASYNC16(sArow + sn,      ga + lh*16,     ok);
            CP_ASYNC16(sArow + sn + 16, ga + lh*16 + 8, ok);
            CP_ASYNC16(sBrow + sn,      gb + lh*16,     16);
            CP_ASYNC16(sBrow + sn + 16, gb + lh*16 + 8, 16);
            CP_COMMIT();
        }
    }
    #pragma unroll
    for (int mt = 0; mt < 4; mt++) {
        int r0 = m0 + wm*64 + mt*16 + (lane >> 2);
        #pragma unroll
        for (int nt = 0; nt < 4; nt++) {
            int c0 = n0 + wn*32 + nt*8 + (lane & 3)*2;
            __half2 h0 = __floats2half2_rn(acc[mt][nt][0], acc[mt][nt][1]);
            __half2 h1 = __floats2half2_rn(acc[mt][nt][2], acc[mt][nt][3]);
            *(uint32_t*)&Y[(size_t)r0*DD + c0]     = *(uint32_t*)&h0;
            *(uint32_t*)&Y[(size_t)(r0+8)*DD + c0] = *(uint32_t*)&h1;
        }
    }
}

// ---------------- out GEMM (fp16, 3-stage, ks-staggered): out = AOh @ Wob + bo ----
__global__ __launch_bounds__(256) void k_out_h(const float* __restrict__ bo,
                                               float* __restrict__ out) {
    extern __shared__ __half smh[];
    uint32_t sbase = s2u(smh);
    int tid = threadIdx.x;
    int lane = tid & 31, wid = tid >> 5;
    int wm = wid & 1, wn = wid >> 1;
    int n0 = blockIdx.x * 128, m0 = blockIdx.y * 128;

    int lr = tid >> 1, lh = tid & 1;
    const __half* aRowPtr = g_AOh  + (size_t)(m0 + lr) * DD;
    const __half* bRowPtr = g_Wobh + (size_t)(n0 + lr) * DD;
    uint32_t sArow = sbase + lr * SROWB + lh * 32;
    uint32_t sBrow = sbase + TILEB + lr * SROWB + lh * 32;

    int aRow = wm*64 + (lane & 15);
    int aU   = lane >> 4;
    int bRow = wn*32 + (lane & 7) + ((lane & 16) >> 1);
    int bU   = (lane >> 3) & 1;
    uint32_t aAddr = sbase + aRow * SROWB + aU * 16;
    uint32_t bAddr = sbase + TILEB + bRow * SROWB + bU * 16;

    float acc[4][4][4] = {};
    const int NT = 16;
    #pragma unroll
    for (int t = 0; t < 2; t++) {
        uint32_t so = (uint32_t)(t * STAGEB);
        const __half* ga = aRowPtr + t*32;
        const __half* gb = bRowPtr + t*32;
        CP_ASYNC16(sArow + so,      ga + lh*16,     16);
        CP_ASYNC16(sArow + so + 16, ga + lh*16 + 8, 16);
        CP_ASYNC16(sBrow + so,      gb + lh*16,     16);
        CP_ASYNC16(sBrow + so + 16, gb + lh*16 + 8, 16);
        CP_COMMIT();
    }
    int ks0 = wid & 1;
    #pragma unroll 1
    for (int t = 0; t < NT; t++) {
        if (t + 1 < NT) { CP_WAIT(1); } else { CP_WAIT(0); }
        __syncthreads();
        uint32_t so = (uint32_t)((t % NSTAGE) * STAGEB);
        #pragma unroll
        for (int kk = 0; kk < 2; kk++) {
            int ks = ks0 ^ kk;
            uint32_t a[4][4], b[4][2];
            #pragma unroll
            for (int mt = 0; mt < 4; mt++)
                ldsm4(a[mt][0], a[mt][1], a[mt][2], a[mt][3],
                      aAddr + so + mt*16*SROWB + 32*ks);
            #pragma unroll
            for (int ntp = 0; ntp < 2; ntp++)
                ldsm4(b[2*ntp][0], b[2*ntp][1], b[2*ntp+1][0], b[2*ntp+1][1],
                      bAddr + so + ntp*16*SROWB + 32*ks);
            #pragma unroll
            for (int mt = 0; mt < 4; mt++)
                #pragma unroll
                for (int nt = 0; nt < 4; nt++)
                    mma_fp16(acc[mt][nt], a[mt], b[nt]);
        }
        if (t + 2 < NT) {
            int tn = t + 2;
            uint32_t sn = (uint32_t)((tn % NSTAGE) * STAGEB);
            const __half* ga = aRowPtr + tn*32;
            const __half* gb = bRowPtr + tn*32;
            CP_ASYNC16(sArow + sn,      ga + lh*16,     16);
            CP_ASYNC16(sArow + sn + 16, ga + lh*16 + 8, 16);
            CP_ASYNC16(sBrow + sn,      gb + lh*16,     16);
            CP_ASYNC16(sBrow + sn + 16, gb + lh*16 + 8, 16);
            CP_COMMIT();
        }
    }
    #pragma unroll
    for (int mt = 0; mt < 4; mt++) {
        int r0 = m0 + wm*64 + mt*16 + (lane >> 2);
        #pragma unroll
        for (int nt = 0; nt < 4; nt++) {
            int c0 = n0 + wn*32 + nt*8 + (lane & 3)*2;
            float2 bb = *(const float2*)&bo[c0];
            *(float2*)&out[(size_t)r0*DD + c0] =
                make_float2(acc[mt][nt][0] + bb.x, acc[mt][nt][1] + bb.y);
            *(float2*)&out[(size_t)(r0+8)*DD + c0] =
                make_float2(acc[mt][nt][2] + bb.x, acc[mt][nt][3] + bb.y);
        }
    }
}

// ---------------- fused LN + attention: one CTA per batch element ----------------
__global__ __launch_bounds__(256) void k_lnattn(
    const float* __restrict__ g0, const float* __restrict__ b0,
    const float* __restrict__ g1, const float* __restrict__ b1,
    const float* __restrict__ g2, const float* __restrict__ b2,
    const float* __restrict__ rel, const float* __restrict__ gsb,
    const float* __restrict__ alpha, const float* __restrict__ bqp)
{
    extern __shared__ __align__(16) char la[];
    __half* qkv = (__half*)la;                  // [3][NSEQ][520]
    float*  scA = (float*)(la + LA_SC);         // [HH][NSEQ][NSEQ]
    float*  pv  = (float*)(la + LA_PV);         // [HH][NSEQ]
    int tid = threadIdx.x;
    int b = blockIdx.x;
    size_t base = (size_t)b * NSEQ * DD;
    int w = tid >> 5, lane = tid & 31;

    if (tid < HH*NSEQ) {
        int h = tid / NSEQ, i = tid - h*NSEQ;
        pv[h*NSEQ + i] = g_P[((size_t)b*NSEQ + i) * HH + h];
    }

    // per-row LN for 3 projections (one warp per row)
    for (int i = w; i < NSEQ; i += 8) {
        float xv[16];
        {
            const __half2* xp = (const __half2*)(g_Xh + base + (size_t)i*DD + lane*16);
            #pragma unroll
            for (int c = 0; c < 8; c++) {
                float2 f = __half22float2(xp[c]);
                xv[2*c] = f.x; xv[2*c+1] = f.y;
            }
        }
        #pragma unroll
        for (int p = 0; p < 3; p++) {
            const float* gg = (p == 0) ? g0 : (p == 1) ? g1 : g2;
            const float* be = (p == 0) ? b0 : (p == 1) ? b1 : b2;
            float yv[16];
            const __half2* yp = (const __half2*)(g_Yh[p] + base + (size_t)i*DD + lane*16);
            float s = 0.f, q = 0.f;
            #pragma unroll
            for (int c = 0; c < 8; c++) {
                float2 f = __half22float2(yp[c]);
                yv[2*c] = f.x; yv[2*c+1] = f.y;
                s += f.x + f.y; q += f.x*f.x + f.y*f.y;
            }
            #pragma unroll
            for (int o = 16; o > 0; o >>= 1) {
                s += __shfl_xor_sync(0xffffffffu, s, o);
                q += __shfl_xor_sync(0xffffffffu, q, o);
            }
            float mean = s * (1.f/512.f);
            float var  = q * (1.f/512.f) - mean*mean;
            float rstd = rsqrtf(var + 1e-5f);
            __half* dst = qkv + (p*NSEQ + i)*520;
            #pragma unroll
            for (int c = 0; c < 8; c++) {
                int d = lane*16 + 2*c;
                float o0 = xv[2*c]   + (yv[2*c]   - mean)*rstd*gg[d]   + be[d];
                float o1 = xv[2*c+1] + (yv[2*c+1] - mean)*rstd*gg[d+1] + be[d+1];
                *(__half2*)(dst + d) = __floats2half2_rn(o0, o1);
            }
        }
    }
    __syncthreads();

    float al = alpha[0];
    // scores for all heads
    for (int idx = tid; idx < HH*NSEQ*NSEQ; idx += 256) {
        int h = idx / (NSEQ*NSEQ);
        int r = idx - h*NSEQ*NSEQ;
        int i = r / NSEQ, j = r - i*NSEQ;
        const __half2* qp = (const __half2*)(qkv + i*520 + h*DKH);
        const __half2* kp = (const __half2*)(qkv + (NSEQ + j)*520 + h*DKH);
        float s = 0.f;
        #pragma unroll
        for (int c = 0; c < 32; c++) {
            float2 a = __half22float2(qp[c]);
            float2 k2 = __half22float2(kp[c]);
            s += a.x*k2.x + a.y*k2.y;
        }
        scA[idx] = s * 0.125f
                 + rel[(i - j + NSEQ - 1)*HH + h]
                 + al * gsb[h*NSEQ*NSEQ + i*NSEQ + j]
                 + pv[h*NSEQ + i] - pv[h*NSEQ + j] + bqp[h];
    }
    __syncthreads();
    // softmax per (h,i) row
    if (tid < HH*NSEQ) {
        float* row = scA + tid*NSEQ;
        float m = -1e30f;
        #pragma unroll
        for (int j = 0; j < NSEQ; j++) m = fmaxf(m, row[j]);
        float s = 0.f;
        #pragma unroll
        for (int j = 0; j < NSEQ; j++) { float e = __expf(row[j] - m); row[j] = e; s += e; }
        float inv = 1.f / s;
        #pragma unroll
        for (int j = 0; j < NSEQ; j++) row[j] *= inv;
    }
    __syncthreads();
    // AV + store
    for (int idx = tid; idx < NSEQ*DD; idx += 256) {
        int i = idx >> 9, d = idx & 511;
        int h = d >> 6;
        const float* sr = scA + (h*NSEQ + i)*NSEQ;
        float o = 0.f;
        #pragma unroll
        for (int j = 0; j < NSEQ; j++)
            o += sr[j] * __half2float(qkv[(2*NSEQ + j)*520 + d]);
        g_AOh[base + (size_t)i*DD + d] = __float2half_rn(o);
    }
}

extern "C" void kernel_launch(void* const* d_in, const int* in_sizes, int n_in,
                              void* d_out, int out_size) {
    const float* x    = (const float*)d_in[0];
    const float* Wq   = (const float*)d_in[1];
    const float* Wk   = (const float*)d_in[2];
    const float* Wv   = (const float*)d_in[3];
    const float* gq_g = (const float*)d_in[4];
    const float* gq_b = (const float*)d_in[5];
    const float* gk_g = (const float*)d_in[6];
    const float* gk_b = (const float*)d_in[7];
    const float* gv_g = (const float*)d_in[8];
    const float* gv_b = (const float*)d_in[9];
    const float* rel  = (const float*)d_in[10];
    const float* gsb  = (const float*)d_in[11];
    const float* alpha= (const float*)d_in[12];
    const float* Wqf  = (const float*)d_in[13];
    const float* bqf  = (const float*)d_in[14];
    const float* Wqp  = (const float*)d_in[15];
    const float* bqp  = (const float*)d_in[16];
    const float* Wo   = (const float*)d_in[17];
    const float* bo   = (const float*)d_in[18];
    float* out = (float*)d_out;

    cudaFuncSetAttribute(k_conv_h, cudaFuncAttributeMaxDynamicSharedMemorySize, SMEM_DYN);
    cudaFuncSetAttribute(k_out_h,  cudaFuncAttributeMaxDynamicSharedMemorySize, SMEM_DYN);
    cudaFuncSetAttribute(k_lnattn, cudaFuncAttributeMaxDynamicSharedMemorySize, LA_TOT);

    k_prepXh<<<(MTOT*DD/4)/256, 256>>>(x);
    k_prepB<<<dim3(KC/256, DD, 3), 256>>>(Wq, Wk, Wv);
    k_prepO<<<(DD*DD)/256, 256>>>(Wo);
    k_prepQf<<<(DQF*DD)/256, 256>>>(Wqf);
    k_qfp_tc<<<MTOT/128, 256>>>(bqf, Wqp);
    k_conv_h<<<dim3(DD/128, MTOT/128, 3), 256, SMEM_DYN>>>(0);
    k_lnattn<<<BB, 256, LA_TOT>>>(gq_g, gq_b, gk_g, gk_b, gv_g, gv_b,
                                  rel, gsb, alpha, bqp);
    k_out_h<<<dim3(DD/128, MTOT/128), 256, SMEM_DYN>>>(bo, out);
}

// round 14
// speedup vs baseline: 1.0704x; 1.0704x over previous
#include <cuda_runtime.h>
#include <cuda_fp16.h>
#include <math.h>
#include <stdint.h>

#define BB   2048
#define NSEQ 20
#define DD   512
#define HH   8
#define DKH  64
#define DQF  64
#define MTOT (BB*NSEQ)     /* 40960 */
#define KC   (3*DD)        /* 1536  */

// ---------------- scratch (no allocations allowed) ----------------
__device__ __half g_Xh [MTOT*DD];     // x in fp16
__device__ __half g_Wbh[3][DD*KC];    // conv B, [p][n*KC + k], k = tap*512+i
__device__ __half g_Wobh[DD*DD];      // out B, [n*DD + k]
__device__ __half g_Wqfh[DQF*DD];     // qf B, [n*DD + k]
__device__ __half g_Yh[3][MTOT*DD];   // conv out (fp16) -> q/k/v after LN+res (in place)
__device__ float  g_P [MTOT*HH];      // p[b,n,h]
__device__ __half g_AOh[MTOT*DD];     // attention output (fp16 for out GEMM)

// ---------------- asm helpers ----------------
__device__ __forceinline__ uint32_t s2u(const void* p) {
    uint32_t a;
    asm("{ .reg .u64 t; cvta.to.shared.u64 t, %1; cvt.u32.u64 %0, t; }" : "=r"(a) : "l"(p));
    return a;
}
#define CP_ASYNC16(s, g, sz) \
    asm volatile("cp.async.cg.shared.global [%0], [%1], 16, %2;" :: "r"(s), "l"(g), "r"(sz))
#define CP_COMMIT() asm volatile("cp.async.commit_group;" ::: "memory")
#define CP_WAIT(n)  asm volatile("cp.async.wait_group %0;" :: "n"(n) : "memory")

__device__ __forceinline__ void ldsm4(uint32_t& r0, uint32_t& r1, uint32_t& r2, uint32_t& r3,
                                      uint32_t addr) {
    asm volatile("ldmatrix.sync.aligned.m8n8.x4.shared.b16 {%0,%1,%2,%3}, [%4];"
                 : "=r"(r0), "=r"(r1), "=r"(r2), "=r"(r3) : "r"(addr));
}
__device__ __forceinline__ void mma_fp16(float* c, const uint32_t* a, const uint32_t* b) {
    asm volatile(
        "mma.sync.aligned.m16n8k16.row.col.f32.f16.f16.f32 "
        "{%0,%1,%2,%3},{%4,%5,%6,%7},{%8,%9},{%0,%1,%2,%3};"
        : "+f"(c[0]), "+f"(c[1]), "+f"(c[2]), "+f"(c[3])
        : "r"(a[0]), "r"(a[1]), "r"(a[2]), "r"(a[3]), "r"(b[0]), "r"(b[1]));
}

// smem tile geometry: rows of 32 halves (64B data) padded to 80B stride
#define SROWB  80
#define TILEB  (128*SROWB)      /* 10240 B per operand tile */
#define STAGEB (2*TILEB)        /* A + B per stage */
#define NSTAGE 3
#define SMEM_DYN (NSTAGE*STAGEB)

// qfp_tc geometry: A 128x32 (10240B) + B 64x32 (5120B) per stage
#define QATILE 10240
#define QSTAGE 15360
#define QARENA (3*QSTAGE)       /* 46080 >= qf(34816)+ws(2048) */

// ---------------- prep kernels ----------------
__global__ void k_prepXh(const float* __restrict__ x) {
    int t = blockIdx.x * 256 + threadIdx.x;     // one float4 per thread
    float4 v = *(const float4*)(x + (size_t)t * 4);
    __half2 h0 = __floats2half2_rn(v.x, v.y);
    __half2 h1 = __floats2half2_rn(v.z, v.w);
    *(uint32_t*)(&g_Xh[(size_t)t*4])     = *(uint32_t*)&h0;
    *(uint32_t*)(&g_Xh[(size_t)t*4 + 2]) = *(uint32_t*)&h1;
}
__global__ void k_prepB(const float* __restrict__ Wq,
                        const float* __restrict__ Wk,
                        const float* __restrict__ Wv) {
    const float* W = (blockIdx.z == 0) ? Wq : (blockIdx.z == 1) ? Wk : Wv;
    int k = blockIdx.x * 256 + threadIdx.x;   // 0..1535
    int n = blockIdx.y;
    int tap = k >> 9, i = k & 511;
    g_Wbh[blockIdx.z][(size_t)n * KC + k] = __float2half_rn(W[(size_t)n * KC + i * 3 + tap]);
}
// merged: Wo transpose (DD*DD elems) + Wqf transpose (DQF*DD elems)
__global__ void k_prepMisc(const float* __restrict__ Wo,
                           const float* __restrict__ Wqf) {
    int t = blockIdx.x * 256 + threadIdx.x;
    if (t < DD*DD) {
        int k = t & 511, n = t >> 9;
        g_Wobh[(size_t)n * DD + k] = __float2half_rn(Wo[(size_t)k * DD + n]);
    } else {
        int u = t - DD*DD;          // 0..DQF*DD-1
        int n = u >> 9, k = u & 511;
        g_Wqfh[(size_t)n * DD + k] = __float2half_rn(Wqf[(size_t)k * DQF + n]);
    }
}

// ---------------- qf/p via tensor cores: qf = tanh(x@Wqf+bqf); p = qf@Wqp ----
__global__ __launch_bounds__(256) void k_qfp_tc(const float* __restrict__ bqf,
                                                const float* __restrict__ Wqp) {
    __shared__ __align__(16) char arena[QARENA];
    uint32_t sbase = s2u(arena);
    int tid = threadIdx.x;
    int lane = tid & 31, wid = tid >> 5;
    int wm = wid & 3, wn = wid >> 2;          // 4m x 2n warps, warp tile 32x32
    int m0 = blockIdx.x * 128;

    int lr = tid >> 1, lh = tid & 1;
    const __half* aRowPtr = g_Xh + (size_t)(m0 + lr) * DD;
    uint32_t sArow = sbase + lr * SROWB + lh * 32;
    int br = (tid & 127) >> 1;                // B rows, threads < 128
    const __half* bRowPtr = g_Wqfh + (size_t)br * DD;
    uint32_t sBrow = sbase + QATILE + br * SROWB + lh * 32;

    uint32_t aAddr = sbase + (wm*32 + (lane & 15)) * SROWB + (lane >> 4) * 16;
    uint32_t bAddr = sbase + QATILE
                   + (wn*32 + (lane & 7) + ((lane & 16) >> 1)) * SROWB
                   + ((lane >> 3) & 1) * 16;

    float acc[2][4][4] = {};
    const int NT = 16;
    #pragma unroll
    for (int t = 0; t < 2; t++) {
        uint32_t so = (uint32_t)(t * QSTAGE);
        const __half* ga = aRowPtr + t*32;
        CP_ASYNC16(sArow + so,      ga + lh*16,     16);
        CP_ASYNC16(sArow + so + 16, ga + lh*16 + 8, 16);
        if (tid < 128) {
            const __half* gb = bRowPtr + t*32;
            CP_ASYNC16(sBrow + so,      gb + lh*16,     16);
            CP_ASYNC16(sBrow + so + 16, gb + lh*16 + 8, 16);
        }
        CP_COMMIT();
    }
    int ks0 = wid & 1;
    #pragma unroll 1
    for (int t = 0; t < NT; t++) {
        if (t + 1 < NT) { CP_WAIT(1); } else { CP_WAIT(0); }
        __syncthreads();
        uint32_t so = (uint32_t)((t % 3) * QSTAGE);
        #pragma unroll
        for (int kk = 0; kk < 2; kk++) {
            int ks = ks0 ^ kk;
            uint32_t a[2][4], b[4][2];
            #pragma unroll
            for (int mt = 0; mt < 2; mt++)
                ldsm4(a[mt][0], a[mt][1], a[mt][2], a[mt][3],
                      aAddr + so + mt*16*SROWB + 32*ks);
            ldsm4(b[0][0], b[0][1], b[1][0], b[1][1], bAddr + so + 32*ks);
            ldsm4(b[2][0], b[2][1], b[3][0], b[3][1], bAddr + so + 16*SROWB + 32*ks);
            #pragma unroll
            for (int mt = 0; mt < 2; mt++)
                #pragma unroll
                for (int nt = 0; nt < 4; nt++)
                    mma_fp16(acc[mt][nt], a[mt], b[nt]);
        }
        if (t + 2 < NT) {
            int tn = t + 2;
            uint32_t sn = (uint32_t)((tn % 3) * QSTAGE);
            const __half* ga = aRowPtr + tn*32;
            CP_ASYNC16(sArow + sn,      ga + lh*16,     16);
            CP_ASYNC16(sArow + sn + 16, ga + lh*16 + 8, 16);
            if (tid < 128) {
                const __half* gb = bRowPtr + tn*32;
                CP_ASYNC16(sBrow + sn,      gb + lh*16,     16);
                CP_ASYNC16(sBrow + sn + 16, gb + lh*16 + 8, 16);
            }
            CP_COMMIT();
        }
    }
    // epilogue: tanh(acc + bqf) -> qfS, then p = qfS @ Wqp
    __syncthreads();
    float* qfS = (float*)arena;               // [128][68]
    float* ws  = (float*)arena + 128*68;      // [64*8]
    #pragma unroll
    for (int mt = 0; mt < 2; mt++) {
        int r = wm*32 + mt*16 + (lane >> 2);
        #pragma unroll
        for (int nt = 0; nt < 4; nt++) {
            int c = wn*32 + nt*8 + (lane & 3)*2;
            float b0 = bqf[c], b1 = bqf[c+1];
            qfS[r*68 + c]       = tanhf(acc[mt][nt][0] + b0);
            qfS[r*68 + c + 1]   = tanhf(acc[mt][nt][1] + b1);
            qfS[(r+8)*68 + c]   = tanhf(acc[mt][nt][2] + b0);
            qfS[(r+8)*68 + c+1] = tanhf(acc[mt][nt][3] + b1);
        }
    }
    ws[tid]       = Wqp[tid];
    ws[tid + 256] = Wqp[tid + 256];
    __syncthreads();
    #pragma unroll
    for (int e = 0; e < 4; e++) {
        int idx = tid + e * 256;
        int r = idx >> 3, h = idx & 7;
        float s = 0.f;
        #pragma unroll 16
        for (int dq = 0; dq < DQF; dq++) s += qfS[r*68 + dq] * ws[dq*HH + h];
        g_P[(size_t)(m0 + r) * HH + h] = s;
    }
}

// ---------------- conv QKV GEMM (fp16 mma.sync, 3-stage, ks-staggered) ----------------
__global__ __launch_bounds__(256) void k_conv_h(int dummy) {
    extern __shared__ __half smh[];
    uint32_t sbase = s2u(smh);
    int tid = threadIdx.x;
    int lane = tid & 31, wid = tid >> 5;
    int wm = wid & 1, wn = wid >> 1;
    int n0 = blockIdx.x * 128, m0 = blockIdx.y * 128, p = blockIdx.z;
    const __half* Wb = g_Wbh[p];
    __half* Y = g_Yh[p];

    int lr = tid >> 1, lh = tid & 1;
    int nrowA = (m0 + lr) % NSEQ;
    const __half* aRowPtr = g_Xh + (size_t)(m0 + lr) * DD;
    const __half* bRowPtr = Wb + (size_t)(n0 + lr) * KC;
    uint32_t sArow = sbase + lr * SROWB + lh * 32;
    uint32_t sBrow = sbase + TILEB + lr * SROWB + lh * 32;

    int aRow = wm*64 + (lane & 15);
    int aU   = lane >> 4;
    int bRow = wn*32 + (lane & 7) + ((lane & 16) >> 1);
    int bU   = (lane >> 3) & 1;
    uint32_t aAddr = sbase + aRow * SROWB + aU * 16;
    uint32_t bAddr = sbase + TILEB + bRow * SROWB + bU * 16;

    float acc[4][4][4] = {};
    const int NT = 48;

    #pragma unroll
    for (int t = 0; t < 2; t++) {
        int tap = t >> 4, ib = (t & 15) * 32;
        uint32_t so = (uint32_t)(t * STAGEB);
        int ok = ((unsigned)(nrowA + tap - 1) < (unsigned)NSEQ) ? 16 : 0;
        const __half* ga = ok ? (aRowPtr + (ptrdiff_t)(tap-1)*DD + ib) : g_Xh;
        const __half* gb = bRowPtr + t*32;
        CP_ASYNC16(sArow + so,      ga + lh*16,     ok);
        CP_ASYNC16(sArow + so + 16, ga + lh*16 + 8, ok);
        CP_ASYNC16(sBrow + so,      gb + lh*16,     16);
        CP_ASYNC16(sBrow + so + 16, gb + lh*16 + 8, 16);
        CP_COMMIT();
    }
    int ks0 = wid & 1;
    #pragma unroll 1
    for (int t = 0; t < NT; t++) {
        if (t + 1 < NT) { CP_WAIT(1); } else { CP_WAIT(0); }
        __syncthreads();
        uint32_t so = (uint32_t)((t % NSTAGE) * STAGEB);
        #pragma unroll
        for (int kk = 0; kk < 2; kk++) {
            int ks = ks0 ^ kk;
            uint32_t a[4][4], b[4][2];
            #pragma unroll
            for (int mt = 0; mt < 4; mt++)
                ldsm4(a[mt][0], a[mt][1], a[mt][2], a[mt][3],
                      aAddr + so + mt*16*SROWB + 32*ks);
            #pragma unroll
            for (int ntp = 0; ntp < 2; ntp++)
                ldsm4(b[2*ntp][0], b[2*ntp][1], b[2*ntp+1][0], b[2*ntp+1][1],
                      bAddr + so + ntp*16*SROWB + 32*ks);
            #pragma unroll
            for (int mt = 0; mt < 4; mt++)
                #pragma unroll
                for (int nt = 0; nt < 4; nt++)
                    mma_fp16(acc[mt][nt], a[mt], b[nt]);
        }
        if (t + 2 < NT) {
            int tn = t + 2, tap = tn >> 4, ib = (tn & 15) * 32;
            uint32_t sn = (uint32_t)((tn % NSTAGE) * STAGEB);
            int ok = ((unsigned)(nrowA + tap - 1) < (unsigned)NSEQ) ? 16 : 0;
            const __half* ga = ok ? (aRowPtr + (ptrdiff_t)(tap-1)*DD + ib) : g_Xh;
            const __half* gb = bRowPtr + tn*32;
            CP_ASYNC16(sArow + sn,      ga + lh*16,     ok);
            CP_ASYNC16(sArow + sn + 16, ga + lh*16 + 8, ok);
            CP_ASYNC16(sBrow + sn,      gb + lh*16,     16);
            CP_ASYNC16(sBrow + sn + 16, gb + lh*16 + 8, 16);
            CP_COMMIT();
        }
    }
    #pragma unroll
    for (int mt = 0; mt < 4; mt++) {
        int r0 = m0 + wm*64 + mt*16 + (lane >> 2);
        #pragma unroll
        for (int nt = 0; nt < 4; nt++) {
            int c0 = n0 + wn*32 + nt*8 + (lane & 3)*2;
            __half2 h0 = __floats2half2_rn(acc[mt][nt][0], acc[mt][nt][1]);
            __half2 h1 = __floats2half2_rn(acc[mt][nt][2], acc[mt][nt][3]);
            *(uint32_t*)&Y[(size_t)r0*DD + c0]     = *(uint32_t*)&h0;
            *(uint32_t*)&Y[(size_t)(r0+8)*DD + c0] = *(uint32_t*)&h1;
        }
    }
}

// ---------------- out GEMM (fp16, 3-stage, ks-staggered): out = AOh @ Wob + bo ----
__global__ __launch_bounds__(256) void k_out_h(const float* __restrict__ bo,
                                               float* __restrict__ out) {
    extern __shared__ __half smh[];
    uint32_t sbase = s2u(smh);
    int tid = threadIdx.x;
    int lane = tid & 31, wid = tid >> 5;
    int wm = wid & 1, wn = wid >> 1;
    int n0 = blockIdx.x * 128, m0 = blockIdx.y * 128;

    int lr = tid >> 1, lh = tid & 1;
    const __half* aRowPtr = g_AOh  + (size_t)(m0 + lr) * DD;
    const __half* bRowPtr = g_Wobh + (size_t)(n0 + lr) * DD;
    uint32_t sArow = sbase + lr * SROWB + lh * 32;
    uint32_t sBrow = sbase + TILEB + lr * SROWB + lh * 32;

    int aRow = wm*64 + (lane & 15);
    int aU   = lane >> 4;
    int bRow = wn*32 + (lane & 7) + ((lane & 16) >> 1);
    int bU   = (lane >> 3) & 1;
    uint32_t aAddr = sbase + aRow * SROWB + aU * 16;
    uint32_t bAddr = sbase + TILEB + bRow * SROWB + bU * 16;

    float acc[4][4][4] = {};
    const int NT = 16;
    #pragma unroll
    for (int t = 0; t < 2; t++) {
        uint32_t so = (uint32_t)(t * STAGEB);
        const __half* ga = aRowPtr + t*32;
        const __half* gb = bRowPtr + t*32;
        CP_ASYNC16(sArow + so,      ga + lh*16,     16);
        CP_ASYNC16(sArow + so + 16, ga + lh*16 + 8, 16);
        CP_ASYNC16(sBrow + so,      gb + lh*16,     16);
        CP_ASYNC16(sBrow + so + 16, gb + lh*16 + 8, 16);
        CP_COMMIT();
    }
    int ks0 = wid & 1;
    #pragma unroll 1
    for (int t = 0; t < NT; t++) {
        if (t + 1 < NT) { CP_WAIT(1); } else { CP_WAIT(0); }
        __syncthreads();
        uint32_t so = (uint32_t)((t % NSTAGE) * STAGEB);
        #pragma unroll
        for (int kk = 0; kk < 2; kk++) {
            int ks = ks0 ^ kk;
            uint32_t a[4][4], b[4][2];
            #pragma unroll
            for (int mt = 0; mt < 4; mt++)
                ldsm4(a[mt][0], a[mt][1], a[mt][2], a[mt][3],
                      aAddr + so + mt*16*SROWB + 32*ks);
            #pragma unroll
            for (int ntp = 0; ntp < 2; ntp++)
                ldsm4(b[2*ntp][0], b[2*ntp][1], b[2*ntp+1][0], b[2*ntp+1][1],
                      bAddr + so + ntp*16*SROWB + 32*ks);
            #pragma unroll
            for (int mt = 0; mt < 4; mt++)
                #pragma unroll
                for (int nt = 0; nt < 4; nt++)
                    mma_fp16(acc[mt][nt], a[mt], b[nt]);
        }
        if (t + 2 < NT) {
            int tn = t + 2;
            uint32_t sn = (uint32_t)((tn % NSTAGE) * STAGEB);
            const __half* ga = aRowPtr + tn*32;
            const __half* gb = bRowPtr + tn*32;
            CP_ASYNC16(sArow + sn,      ga + lh*16,     16);
            CP_ASYNC16(sArow + sn + 16, ga + lh*16 + 8, 16);
            CP_ASYNC16(sBrow + sn,      gb + lh*16,     16);
            CP_ASYNC16(sBrow + sn + 16, gb + lh*16 + 8, 16);
            CP_COMMIT();
        }
    }
    #pragma unroll
    for (int mt = 0; mt < 4; mt++) {
        int r0 = m0 + wm*64 + mt*16 + (lane >> 2);
        #pragma unroll
        for (int nt = 0; nt < 4; nt++) {
            int c0 = n0 + wn*32 + nt*8 + (lane & 3)*2;
            float2 bb = *(const float2*)&bo[c0];
            *(float2*)&out[(size_t)r0*DD + c0] =
                make_float2(acc[mt][nt][0] + bb.x, acc[mt][nt][1] + bb.y);
            *(float2*)&out[(size_t)(r0+8)*DD + c0] =
                make_float2(acc[mt][nt][2] + bb.x, acc[mt][nt][3] + bb.y);
        }
    }
}

// ---------------- LayerNorm + residual, all 3 projections per block ----------------
__global__ __launch_bounds__(128) void k_ln3(const float* __restrict__ g0, const float* __restrict__ b0,
                                             const float* __restrict__ g1, const float* __restrict__ b1,
                                             const float* __restrict__ g2, const float* __restrict__ b2) {
    int r = blockIdx.x;
    int tid = threadIdx.x;                 // 128 threads, 4 elems each
    const __half* xh = g_Xh + (size_t)r * DD;
    __shared__ float rs[3][4], rq[3][4], mv[3][2];

    __half2 xh0 = *(const __half2*)&xh[tid*4];
    __half2 xh1 = *(const __half2*)&xh[tid*4+2];
    float2 xv0 = __half22float2(xh0);
    float2 xv1 = __half22float2(xh1);

    float av[3][4];
    #pragma unroll
    for (int p = 0; p < 3; p++) {
        const __half* y = g_Yh[p] + (size_t)r * DD;
        __half2 h0 = *(const __half2*)&y[tid*4];
        __half2 h1 = *(const __half2*)&y[tid*4+2];
        float2 a = __half22float2(h0);
        float2 c = __half22float2(h1);
        av[p][0] = a.x; av[p][1] = a.y; av[p][2] = c.x; av[p][3] = c.y;
        float s = a.x + a.y + c.x + c.y;
        float q = a.x*a.x + a.y*a.y + c.x*c.x + c.y*c.y;
        #pragma unroll
        for (int o = 16; o > 0; o >>= 1) {
            s += __shfl_down_sync(0xffffffffu, s, o);
            q += __shfl_down_sync(0xffffffffu, q, o);
        }
        if ((tid & 31) == 0) { rs[p][tid>>5] = s; rq[p][tid>>5] = q; }
    }
    __syncthreads();
    if (tid < 3) {
        float ts = rs[tid][0]+rs[tid][1]+rs[tid][2]+rs[tid][3];
        float tq = rq[tid][0]+rq[tid][1]+rq[tid][2]+rq[tid][3];
        float mean = ts * (1.f/512.f);
        float var  = tq * (1.f/512.f) - mean*mean;
        mv[tid][0] = mean; mv[tid][1] = rsqrtf(var + 1e-5f);
    }
    __syncthreads();
    #pragma unroll
    for (int p = 0; p < 3; p++) {
        const float* gg = (p == 0) ? g0 : (p == 1) ? g1 : g2;
        const float* be = (p == 0) ? b0 : (p == 1) ? b1 : b2;
        float mean = mv[p][0], rstd = mv[p][1];
        float o0 = xv0.x + (av[p][0] - mean)*rstd*gg[tid*4+0] + be[tid*4+0];
        float o1 = xv0.y + (av[p][1] - mean)*rstd*gg[tid*4+1] + be[tid*4+1];
        float o2 = xv1.x + (av[p][2] - mean)*rstd*gg[tid*4+2] + be[tid*4+2];
        float o3 = xv1.y + (av[p][3] - mean)*rstd*gg[tid*4+3] + be[tid*4+3];
        __half2 w0 = __floats2half2_rn(o0, o1);
        __half2 w1 = __floats2half2_rn(o2, o3);
        __half* y = g_Yh[p] + (size_t)r * DD;
        *(__half2*)&y[tid*4]   = w0;
        *(__half2*)&y[tid*4+2] = w1;
    }
}

// ---------------- attention per (b,h), fully smem-resident ----------------
__global__ __launch_bounds__(128) void k_attn(const float* __restrict__ rel,
                                              const float* __restrict__ gsb,
                                              const float* __restrict__ alpha,
                                              const float* __restrict__ bqp) {
    __shared__ float qs[NSEQ][72], ks[NSEQ][72], vs[NSEQ][72];
    __shared__ float sc[NSEQ][NSEQ];
    __shared__ float pv[NSEQ];
    int tid = threadIdx.x;
    int b = blockIdx.x >> 3, h = blockIdx.x & 7;
    size_t base = (size_t)b * NSEQ * DD + (size_t)h * DKH;
    #pragma unroll
    for (int l = 0; l < 5; l++) {
        int idx = tid + l * 128;          // 0..639 half2 per array
        int i = idx >> 5, d = (idx & 31) * 2;
        float2 fq = __half22float2(*(const __half2*)&g_Yh[0][base + (size_t)i*DD + d]);
        float2 fk = __half22float2(*(const __half2*)&g_Yh[1][base + (size_t)i*DD + d]);
        float2 fv = __half22float2(*(const __half2*)&g_Yh[2][base + (size_t)i*DD + d]);
        qs[i][d] = fq.x; qs[i][d+1] = fq.y;
        ks[i][d] = fk.x; ks[i][d+1] = fk.y;
        vs[i][d] = fv.x; vs[i][d+1] = fv.y;
    }
    if (tid < NSEQ) pv[tid] = g_P[((size_t)b*NSEQ + tid)*HH + h];
    __syncthreads();
    float al = alpha[0], bq = bqp[h];
    for (int idx = tid; idx < NSEQ*NSEQ; idx += 128) {
        int i = idx / NSEQ, j = idx - i * NSEQ;
        float s = 0.f;
        #pragma unroll
        for (int dv = 0; dv < 16; dv++) {
            float4 a = *(const float4*)&qs[i][dv*4];
            float4 c = *(const float4*)&ks[j][dv*4];
            s += a.x*c.x + a.y*c.y + a.z*c.z + a.w*c.w;
        }
        sc[i][j] = s * 0.125f
                 + rel[(i - j + NSEQ - 1) * HH + h]
                 + al * gsb[h * NSEQ*NSEQ + i * NSEQ + j]
                 + pv[i] - pv[j] + bq;
    }
    __syncthreads();
    if (tid < NSEQ) {
        float m = -1e30f;
        #pragma unroll
        for (int j = 0; j < NSEQ; j++) m = fmaxf(m, sc[tid][j]);
        float s = 0.f;
        #pragma unroll
        for (int j = 0; j < NSEQ; j++) { float e = __expf(sc[tid][j] - m); sc[tid][j] = e; s += e; }
        float inv = 1.f / s;
        #pragma unroll
        for (int j = 0; j < NSEQ; j++) sc[tid][j] *= inv;
    }
    __syncthreads();
    #pragma unroll
    for (int l = 0; l < 10; l++) {
        int idx = tid + l * 128;
        int i = idx >> 6, d = idx & 63;
        float o = 0.f;
        #pragma unroll
        for (int j = 0; j < NSEQ; j++) o += sc[i][j] * vs[j][d];
        g_AOh[base + (size_t)i*DD + d] = __float2half_rn(o);
    }
}

extern "C" void kernel_launch(void* const* d_in, const int* in_sizes, int n_in,
                              void* d_out, int out_size) {
    const float* x    = (const float*)d_in[0];
    const float* Wq   = (const float*)d_in[1];
    const float* Wk   = (const float*)d_in[2];
    const float* Wv   = (const float*)d_in[3];
    const float* gq_g = (const float*)d_in[4];
    const float* gq_b = (const float*)d_in[5];
    const float* gk_g = (const float*)d_in[6];
    const float* gk_b = (const float*)d_in[7];
    const float* gv_g = (const float*)d_in[8];
    const float* gv_b = (const float*)d_in[9];
    const float* rel  = (const float*)d_in[10];
    const float* gsb  = (const float*)d_in[11];
    const float* alpha= (const float*)d_in[12];
    const float* Wqf  = (const float*)d_in[13];
    const float* bqf  = (const float*)d_in[14];
    const float* Wqp  = (const float*)d_in[15];
    const float* bqp  = (const float*)d_in[16];
    const float* Wo   = (const float*)d_in[17];
    const float* bo   = (const float*)d_in[18];
    float* out = (float*)d_out;

    cudaFuncSetAttribute(k_conv_h, cudaFuncAttributeMaxDynamicSharedMemorySize, SMEM_DYN);
    cudaFuncSetAttribute(k_out_h,  cudaFuncAttributeMaxDynamicSharedMemorySize, SMEM_DYN);

    k_prepXh<<<(MTOT*DD/4)/256, 256>>>(x);
    k_prepB<<<dim3(KC/256, DD, 3), 256>>>(Wq, Wk, Wv);
    k_prepMisc<<<(DD*DD + DQF*DD)/256, 256>>>(Wo, Wqf);
    k_qfp_tc<<<MTOT/128, 256>>>(bqf, Wqp);
    k_conv_h<<<dim3(DD/128, MTOT/128, 3), 256, SMEM_DYN>>>(0);
    k_ln3<<<MTOT, 128>>>(gq_g, gq_b, gk_g, gk_b, gv_g, gv_b);
    k_attn<<<BB*HH, 128>>>(rel, gsb, alpha, bqp);
    k_out_h<<<dim3(DD/128, MTOT/128), 256, SMEM_DYN>>>(bo, out);
}

// round 15
// speedup vs baseline: 1.0722x; 1.0017x over previous
#include <cuda_runtime.h>
#include <cuda_fp16.h>
#include <math.h>
#include <stdint.h>

#define BB   2048
#define NSEQ 20
#define DD   512
#define HH   8
#define DKH  64
#define DQF  64
#define MTOT (BB*NSEQ)     /* 40960 */
#define KC   (3*DD)        /* 1536  */

// ---------------- scratch (no allocations allowed) ----------------
__device__ __half g_Xh [MTOT*DD];     // x in fp16
__device__ __half g_Wbh[3][DD*KC];    // conv B, [p][n*KC + k], k = tap*512+i
__device__ __half g_Wobh[DD*DD];      // out B, [n*DD + k]
__device__ __half g_Wqfh[DQF*DD];     // qf B, [n*DD + k]
__device__ __half g_Yh[3][MTOT*DD];   // conv out (fp16) -> q/k/v after LN+res (in place)
__device__ float  g_P [MTOT*HH];      // p[b,n,h]
__device__ __half g_AOh[MTOT*DD];     // attention output (fp16 for out GEMM)

// ---------------- asm helpers ----------------
__device__ __forceinline__ uint32_t s2u(const void* p) {
    uint32_t a;
    asm("{ .reg .u64 t; cvta.to.shared.u64 t, %1; cvt.u32.u64 %0, t; }" : "=r"(a) : "l"(p));
    return a;
}
#define CP_ASYNC16(s, g, sz) \
    asm volatile("cp.async.cg.shared.global [%0], [%1], 16, %2;" :: "r"(s), "l"(g), "r"(sz))
#define CP_COMMIT() asm volatile("cp.async.commit_group;" ::: "memory")
#define CP_WAIT(n)  asm volatile("cp.async.wait_group %0;" :: "n"(n) : "memory")

__device__ __forceinline__ void ldsm4(uint32_t& r0, uint32_t& r1, uint32_t& r2, uint32_t& r3,
                                      uint32_t addr) {
    asm volatile("ldmatrix.sync.aligned.m8n8.x4.shared.b16 {%0,%1,%2,%3}, [%4];"
                 : "=r"(r0), "=r"(r1), "=r"(r2), "=r"(r3) : "r"(addr));
}
__device__ __forceinline__ void mma_fp16(float* c, const uint32_t* a, const uint32_t* b) {
    asm volatile(
        "mma.sync.aligned.m16n8k16.row.col.f32.f16.f16.f32 "
        "{%0,%1,%2,%3},{%4,%5,%6,%7},{%8,%9},{%0,%1,%2,%3};"
        : "+f"(c[0]), "+f"(c[1]), "+f"(c[2]), "+f"(c[3])
        : "r"(a[0]), "r"(a[1]), "r"(a[2]), "r"(a[3]), "r"(b[0]), "r"(b[1]));
}

// smem tile geometry: rows of 32 halves (64B data) padded to 80B stride
#define SROWB  80
#define TILEB  (128*SROWB)      /* 10240 B per operand tile */
#define STAGEB (2*TILEB)        /* A + B per stage */
#define NSTAGE 3
#define SMEM_DYN (NSTAGE*STAGEB)

// conv: 4-stage pipeline
#define CNSTG  4
#define SMEM_DYN4 (CNSTG*STAGEB)   /* 81920 */

// qfp_tc geometry: A 128x32 (10240B) + B 64x32 (5120B) per stage
#define QATILE 10240
#define QSTAGE 15360
#define QARENA (3*QSTAGE)       /* 46080 >= qf(34816)+ws(2048) */

// ---------------- prep kernels ----------------
__global__ void k_prepXh(const float* __restrict__ x) {
    int t = blockIdx.x * 256 + threadIdx.x;     // one float4 per thread
    float4 v = *(const float4*)(x + (size_t)t * 4);
    __half2 h0 = __floats2half2_rn(v.x, v.y);
    __half2 h1 = __floats2half2_rn(v.z, v.w);
    *(uint32_t*)(&g_Xh[(size_t)t*4])     = *(uint32_t*)&h0;
    *(uint32_t*)(&g_Xh[(size_t)t*4 + 2]) = *(uint32_t*)&h1;
}
__global__ void k_prepB(const float* __restrict__ Wq,
                        const float* __restrict__ Wk,
                        const float* __restrict__ Wv) {
    const float* W = (blockIdx.z == 0) ? Wq : (blockIdx.z == 1) ? Wk : Wv;
    int k = blockIdx.x * 256 + threadIdx.x;   // 0..1535
    int n = blockIdx.y;
    int tap = k >> 9, i = k & 511;
    g_Wbh[blockIdx.z][(size_t)n * KC + k] = __float2half_rn(W[(size_t)n * KC + i * 3 + tap]);
}
// merged: Wo transpose (DD*DD elems) + Wqf transpose (DQF*DD elems)
__global__ void k_prepMisc(const float* __restrict__ Wo,
                           const float* __restrict__ Wqf) {
    int t = blockIdx.x * 256 + threadIdx.x;
    if (t < DD*DD) {
        int k = t & 511, n = t >> 9;
        g_Wobh[(size_t)n * DD + k] = __float2half_rn(Wo[(size_t)k * DD + n]);
    } else {
        int u = t - DD*DD;          // 0..DQF*DD-1
        int n = u >> 9, k = u & 511;
        g_Wqfh[(size_t)n * DD + k] = __float2half_rn(Wqf[(size_t)k * DQF + n]);
    }
}

// ---------------- qf/p via tensor cores: qf = tanh(x@Wqf+bqf); p = qf@Wqp ----
__global__ __launch_bounds__(256) void k_qfp_tc(const float* __restrict__ bqf,
                                                const float* __restrict__ Wqp) {
    __shared__ __align__(16) char arena[QARENA];
    uint32_t sbase = s2u(arena);
    int tid = threadIdx.x;
    int lane = tid & 31, wid = tid >> 5;
    int wm = wid & 3, wn = wid >> 2;          // 4m x 2n warps, warp tile 32x32
    int m0 = blockIdx.x * 128;

    int lr = tid >> 1, lh = tid & 1;
    const __half* aRowPtr = g_Xh + (size_t)(m0 + lr) * DD;
    uint32_t sArow = sbase + lr * SROWB + lh * 32;
    int br = (tid & 127) >> 1;                // B rows, threads < 128
    const __half* bRowPtr = g_Wqfh + (size_t)br * DD;
    uint32_t sBrow = sbase + QATILE + br * SROWB + lh * 32;

    uint32_t aAddr = sbase + (wm*32 + (lane & 15)) * SROWB + (lane >> 4) * 16;
    uint32_t bAddr = sbase + QATILE
                   + (wn*32 + (lane & 7) + ((lane & 16) >> 1)) * SROWB
                   + ((lane >> 3) & 1) * 16;

    float acc[2][4][4] = {};
    const int NT = 16;
    #pragma unroll
    for (int t = 0; t < 2; t++) {
        uint32_t so = (uint32_t)(t * QSTAGE);
        const __half* ga = aRowPtr + t*32;
        CP_ASYNC16(sArow + so,      ga + lh*16,     16);
        CP_ASYNC16(sArow + so + 16, ga + lh*16 + 8, 16);
        if (tid < 128) {
            const __half* gb = bRowPtr + t*32;
            CP_ASYNC16(sBrow + so,      gb + lh*16,     16);
            CP_ASYNC16(sBrow + so + 16, gb + lh*16 + 8, 16);
        }
        CP_COMMIT();
    }
    int ks0 = wid & 1;
    #pragma unroll 1
    for (int t = 0; t < NT; t++) {
        if (t + 1 < NT) { CP_WAIT(1); } else { CP_WAIT(0); }
        __syncthreads();
        uint32_t so = (uint32_t)((t % 3) * QSTAGE);
        #pragma unroll
        for (int kk = 0; kk < 2; kk++) {
            int ks = ks0 ^ kk;
            uint32_t a[2][4], b[4][2];
            #pragma unroll
            for (int mt = 0; mt < 2; mt++)
                ldsm4(a[mt][0], a[mt][1], a[mt][2], a[mt][3],
                      aAddr + so + mt*16*SROWB + 32*ks);
            ldsm4(b[0][0], b[0][1], b[1][0], b[1][1], bAddr + so + 32*ks);
            ldsm4(b[2][0], b[2][1], b[3][0], b[3][1], bAddr + so + 16*SROWB + 32*ks);
            #pragma unroll
            for (int mt = 0; mt < 2; mt++)
                #pragma unroll
                for (int nt = 0; nt < 4; nt++)
                    mma_fp16(acc[mt][nt], a[mt], b[nt]);
        }
        if (t + 2 < NT) {
            int tn = t + 2;
            uint32_t sn = (uint32_t)((tn % 3) * QSTAGE);
            const __half* ga = aRowPtr + tn*32;
            CP_ASYNC16(sArow + sn,      ga + lh*16,     16);
            CP_ASYNC16(sArow + sn + 16, ga + lh*16 + 8, 16);
            if (tid < 128) {
                const __half* gb = bRowPtr + tn*32;
                CP_ASYNC16(sBrow + sn,      gb + lh*16,     16);
                CP_ASYNC16(sBrow + sn + 16, gb + lh*16 + 8, 16);
            }
            CP_COMMIT();
        }
    }
    // epilogue: tanh(acc + bqf) -> qfS, then p = qfS @ Wqp
    __syncthreads();
    float* qfS = (float*)arena;               // [128][68]
    float* ws  = (float*)arena + 128*68;      // [64*8]
    #pragma unroll
    for (int mt = 0; mt < 2; mt++) {
        int r = wm*32 + mt*16 + (lane >> 2);
        #pragma unroll
        for (int nt = 0; nt < 4; nt++) {
            int c = wn*32 + nt*8 + (lane & 3)*2;
            float b0 = bqf[c], b1 = bqf[c+1];
            qfS[r*68 + c]       = tanhf(acc[mt][nt][0] + b0);
            qfS[r*68 + c + 1]   = tanhf(acc[mt][nt][1] + b1);
            qfS[(r+8)*68 + c]   = tanhf(acc[mt][nt][2] + b0);
            qfS[(r+8)*68 + c+1] = tanhf(acc[mt][nt][3] + b1);
        }
    }
    ws[tid]       = Wqp[tid];
    ws[tid + 256] = Wqp[tid + 256];
    __syncthreads();
    #pragma unroll
    for (int e = 0; e < 4; e++) {
        int idx = tid + e * 256;
        int r = idx >> 3, h = idx & 7;
        float s = 0.f;
        #pragma unroll 16
        for (int dq = 0; dq < DQF; dq++) s += qfS[r*68 + dq] * ws[dq*HH + h];
        g_P[(size_t)(m0 + r) * HH + h] = s;
    }
}

// ---------------- conv QKV GEMM (fp16 mma.sync, 4-stage, ks-staggered) ----------------
__global__ __launch_bounds__(256) void k_conv_h(int dummy) {
    extern __shared__ __half smh[];
    uint32_t sbase = s2u(smh);
    int tid = threadIdx.x;
    int lane = tid & 31, wid = tid >> 5;
    int wm = wid & 1, wn = wid >> 1;
    int n0 = blockIdx.x * 128, m0 = blockIdx.y * 128, p = blockIdx.z;
    const __half* Wb = g_Wbh[p];
    __half* Y = g_Yh[p];

    int lr = tid >> 1, lh = tid & 1;
    int nrowA = (m0 + lr) % NSEQ;
    const __half* aRowPtr = g_Xh + (size_t)(m0 + lr) * DD;
    const __half* bRowPtr = Wb + (size_t)(n0 + lr) * KC;
    uint32_t sArow = sbase + lr * SROWB + lh * 32;
    uint32_t sBrow = sbase + TILEB + lr * SROWB + lh * 32;

    int aRow = wm*64 + (lane & 15);
    int aU   = lane >> 4;
    int bRow = wn*32 + (lane & 7) + ((lane & 16) >> 1);
    int bU   = (lane >> 3) & 1;
    uint32_t aAddr = sbase + aRow * SROWB + aU * 16;
    uint32_t bAddr = sbase + TILEB + bRow * SROWB + bU * 16;

    float acc[4][4][4] = {};
    const int NT = 48;

    // prologue: stages 0..2
    #pragma unroll
    for (int t = 0; t < 3; t++) {
        int tap = t >> 4, ib = (t & 15) * 32;
        uint32_t so = (uint32_t)(t * STAGEB);
        int ok = ((unsigned)(nrowA + tap - 1) < (unsigned)NSEQ) ? 16 : 0;
        const __half* ga = ok ? (aRowPtr + (ptrdiff_t)(tap-1)*DD + ib) : g_Xh;
        const __half* gb = bRowPtr + t*32;
        CP_ASYNC16(sArow + so,      ga + lh*16,     ok);
        CP_ASYNC16(sArow + so + 16, ga + lh*16 + 8, ok);
        CP_ASYNC16(sBrow + so,      gb + lh*16,     16);
        CP_ASYNC16(sBrow + so + 16, gb + lh*16 + 8, 16);
        CP_COMMIT();
    }
    int ks0 = wid & 1;
    #pragma unroll 1
    for (int t = 0; t < NT; t++) {
        CP_WAIT(2);
        __syncthreads();
        uint32_t so = (uint32_t)((t & (CNSTG-1)) * STAGEB);
        #pragma unroll
        for (int kk = 0; kk < 2; kk++) {
            int ks = ks0 ^ kk;
            uint32_t a[4][4], b[4][2];
            #pragma unroll
            for (int mt = 0; mt < 4; mt++)
                ldsm4(a[mt][0], a[mt][1], a[mt][2], a[mt][3],
                      aAddr + so + mt*16*SROWB + 32*ks);
            #pragma unroll
            for (int ntp = 0; ntp < 2; ntp++)
                ldsm4(b[2*ntp][0], b[2*ntp][1], b[2*ntp+1][0], b[2*ntp+1][1],
                      bAddr + so + ntp*16*SROWB + 32*ks);
            #pragma unroll
            for (int mt = 0; mt < 4; mt++)
                #pragma unroll
                for (int nt = 0; nt < 4; nt++)
                    mma_fp16(acc[mt][nt], a[mt], b[nt]);
        }
        if (t + 3 < NT) {
            int tn = t + 3, tap = tn >> 4, ib = (tn & 15) * 32;
            uint32_t sn = (uint32_t)((tn & (CNSTG-1)) * STAGEB);
            int ok = ((unsigned)(nrowA + tap - 1) < (unsigned)NSEQ) ? 16 : 0;
            const __half* ga = ok ? (aRowPtr + (ptrdiff_t)(tap-1)*DD + ib) : g_Xh;
            const __half* gb = bRowPtr + tn*32;
            CP_ASYNC16(sArow + sn,      ga + lh*16,     ok);
            CP_ASYNC16(sArow + sn + 16, ga + lh*16 + 8, ok);
            CP_ASYNC16(sBrow + sn,      gb + lh*16,     16);
            CP_ASYNC16(sBrow + sn + 16, gb + lh*16 + 8, 16);
        }
        CP_COMMIT();   // empty group on tail keeps wait_group(2) bookkeeping exact
    }
    #pragma unroll
    for (int mt = 0; mt < 4; mt++) {
        int r0 = m0 + wm*64 + mt*16 + (lane >> 2);
        #pragma unroll
        for (int nt = 0; nt < 4; nt++) {
            int c0 = n0 + wn*32 + nt*8 + (lane & 3)*2;
            __half2 h0 = __floats2half2_rn(acc[mt][nt][0], acc[mt][nt][1]);
            __half2 h1 = __floats2half2_rn(acc[mt][nt][2], acc[mt][nt][3]);
            *(uint32_t*)&Y[(size_t)r0*DD + c0]     = *(uint32_t*)&h0;
            *(uint32_t*)&Y[(size_t)(r0+8)*DD + c0] = *(uint32_t*)&h1;
        }
    }
}

// ---------------- out GEMM (fp16, 3-stage, ks-staggered): out = AOh @ Wob + bo ----
__global__ __launch_bounds__(256) void k_out_h(const float* __restrict__ bo,
                                               float* __restrict__ out) {
    extern __shared__ __half smh[];
    uint32_t sbase = s2u(smh);
    int tid = threadIdx.x;
    int lane = tid & 31, wid = tid >> 5;
    int wm = wid & 1, wn = wid >> 1;
    int n0 = blockIdx.x * 128, m0 = blockIdx.y * 128;

    int lr = tid >> 1, lh = tid & 1;
    const __half* aRowPtr = g_AOh  + (size_t)(m0 + lr) * DD;
    const __half* bRowPtr = g_Wobh + (size_t)(n0 + lr) * DD;
    uint32_t sArow = sbase + lr * SROWB + lh * 32;
    uint32_t sBrow = sbase + TILEB + lr * SROWB + lh * 32;

    int aRow = wm*64 + (lane & 15);
    int aU   = lane >> 4;
    int bRow = wn*32 + (lane & 7) + ((lane & 16) >> 1);
    int bU   = (lane >> 3) & 1;
    uint32_t aAddr = sbase + aRow * SROWB + aU * 16;
    uint32_t bAddr = sbase + TILEB + bRow * SROWB + bU * 16;

    float acc[4][4][4] = {};
    const int NT = 16;
    #pragma unroll
    for (int t = 0; t < 2; t++) {
        uint32_t so = (uint32_t)(t * STAGEB);
        const __half* ga = aRowPtr + t*32;
        const __half* gb = bRowPtr + t*32;
        CP_ASYNC16(sArow + so,      ga + lh*16,     16);
        CP_ASYNC16(sArow + so + 16, ga + lh*16 + 8, 16);
        CP_ASYNC16(sBrow + so,      gb + lh*16,     16);
        CP_ASYNC16(sBrow + so + 16, gb + lh*16 + 8, 16);
        CP_COMMIT();
    }
    int ks0 = wid & 1;
    #pragma unroll 1
    for (int t = 0; t < NT; t++) {
        if (t + 1 < NT) { CP_WAIT(1); } else { CP_WAIT(0); }
        __syncthreads();
        uint32_t so = (uint32_t)((t % NSTAGE) * STAGEB);
        #pragma unroll
        for (int kk = 0; kk < 2; kk++) {
            int ks = ks0 ^ kk;
            uint32_t a[4][4], b[4][2];
            #pragma unroll
            for (int mt = 0; mt < 4; mt++)
                ldsm4(a[mt][0], a[mt][1], a[mt][2], a[mt][3],
                      aAddr + so + mt*16*SROWB + 32*ks);
            #pragma unroll
            for (int ntp = 0; ntp < 2; ntp++)
                ldsm4(b[2*ntp][0], b[2*ntp][1], b[2*ntp+1][0], b[2*ntp+1][1],
                      bAddr + so + ntp*16*SROWB + 32*ks);
            #pragma unroll
            for (int mt = 0; mt < 4; mt++)
                #pragma unroll
                for (int nt = 0; nt < 4; nt++)
                    mma_fp16(acc[mt][nt], a[mt], b[nt]);
        }
        if (t + 2 < NT) {
            int tn = t + 2;
            uint32_t sn = (uint32_t)((tn % NSTAGE) * STAGEB);
            const __half* ga = aRowPtr + tn*32;
            const __half* gb = bRowPtr + tn*32;
            CP_ASYNC16(sArow + sn,      ga + lh*16,     16);
            CP_ASYNC16(sArow + sn + 16, ga + lh*16 + 8, 16);
            CP_ASYNC16(sBrow + sn,      gb + lh*16,     16);
            CP_ASYNC16(sBrow + sn + 16, gb + lh*16 + 8, 16);
            CP_COMMIT();
        }
    }
    #pragma unroll
    for (int mt = 0; mt < 4; mt++) {
        int r0 = m0 + wm*64 + mt*16 + (lane >> 2);
        #pragma unroll
        for (int nt = 0; nt < 4; nt++) {
            int c0 = n0 + wn*32 + nt*8 + (lane & 3)*2;
            float2 bb = *(const float2*)&bo[c0];
            *(float2*)&out[(size_t)r0*DD + c0] =
                make_float2(acc[mt][nt][0] + bb.x, acc[mt][nt][1] + bb.y);
            *(float2*)&out[(size_t)(r0+8)*DD + c0] =
                make_float2(acc[mt][nt][2] + bb.x, acc[mt][nt][3] + bb.y);
        }
    }
}

// ---------------- LayerNorm + residual, all 3 projections per block ----------------
__global__ __launch_bounds__(128) void k_ln3(const float* __restrict__ g0, const float* __restrict__ b0,
                                             const float* __restrict__ g1, const float* __restrict__ b1,
                                             const float* __restrict__ g2, const float* __restrict__ b2) {
    int r = blockIdx.x;
    int tid = threadIdx.x;                 // 128 threads, 4 elems each
    const __half* xh = g_Xh + (size_t)r * DD;
    __shared__ float rs[3][4], rq[3][4], mv[3][2];

    __half2 xh0 = *(const __half2*)&xh[tid*4];
    __half2 xh1 = *(const __half2*)&xh[tid*4+2];
    float2 xv0 = __half22float2(xh0);
    float2 xv1 = __half22float2(xh1);

    float av[3][4];
    #pragma unroll
    for (int p = 0; p < 3; p++) {
        const __half* y = g_Yh[p] + (size_t)r * DD;
        __half2 h0 = *(const __half2*)&y[tid*4];
        __half2 h1 = *(const __half2*)&y[tid*4+2];
        float2 a = __half22float2(h0);
        float2 c = __half22float2(h1);
        av[p][0] = a.x; av[p][1] = a.y; av[p][2] = c.x; av[p][3] = c.y;
        float s = a.x + a.y + c.x + c.y;
        float q = a.x*a.x + a.y*a.y + c.x*c.x + c.y*c.y;
        #pragma unroll
        for (int o = 16; o > 0; o >>= 1) {
            s += __shfl_down_sync(0xffffffffu, s, o);
            q += __shfl_down_sync(0xffffffffu, q, o);
        }
        if ((tid & 31) == 0) { rs[p][tid>>5] = s; rq[p][tid>>5] = q; }
    }
    __syncthreads();
    if (tid < 3) {
        float ts = rs[tid][0]+rs[tid][1]+rs[tid][2]+rs[tid][3];
        float tq = rq[tid][0]+rq[tid][1]+rq[tid][2]+rq[tid][3];
        float mean = ts * (1.f/512.f);
        float var  = tq * (1.f/512.f) - mean*mean;
        mv[tid][0] = mean; mv[tid][1] = rsqrtf(var + 1e-5f);
    }
    __syncthreads();
    #pragma unroll
    for (int p = 0; p < 3; p++) {
        const float* gg = (p == 0) ? g0 : (p == 1) ? g1 : g2;
        const float* be = (p == 0) ? b0 : (p == 1) ? b1 : b2;
        float mean = mv[p][0], rstd = mv[p][1];
        float o0 = xv0.x + (av[p][0] - mean)*rstd*gg[tid*4+0] + be[tid*4+0];
        float o1 = xv0.y + (av[p][1] - mean)*rstd*gg[tid*4+1] + be[tid*4+1];
        float o2 = xv1.x + (av[p][2] - mean)*rstd*gg[tid*4+2] + be[tid*4+2];
        float o3 = xv1.y + (av[p][3] - mean)*rstd*gg[tid*4+3] + be[tid*4+3];
        __half2 w0 = __floats2half2_rn(o0, o1);
        __half2 w1 = __floats2half2_rn(o2, o3);
        __half* y = g_Yh[p] + (size_t)r * DD;
        *(__half2*)&y[tid*4]   = w0;
        *(__half2*)&y[tid*4+2] = w1;
    }
}

// ---------------- attention per (b,h), fully smem-resident ----------------
__global__ __launch_bounds__(128) void k_attn(const float* __restrict__ rel,
                                              const float* __restrict__ gsb,
                                              const float* __restrict__ alpha,
                                              const float* __restrict__ bqp) {
    __shared__ float qs[NSEQ][72], ks[NSEQ][72], vs[NSEQ][72];
    __shared__ float sc[NSEQ][NSEQ];
    __shared__ float pv[NSEQ];
    int tid = threadIdx.x;
    int b = blockIdx.x >> 3, h = blockIdx.x & 7;
    size_t base = (size_t)b * NSEQ * DD + (size_t)h * DKH;
    #pragma unroll
    for (int l = 0; l < 5; l++) {
        int idx = tid + l * 128;          // 0..639 half2 per array
        int i = idx >> 5, d = (idx & 31) * 2;
        float2 fq = __half22float2(*(const __half2*)&g_Yh[0][base + (size_t)i*DD + d]);
        float2 fk = __half22float2(*(const __half2*)&g_Yh[1][base + (size_t)i*DD + d]);
        float2 fv = __half22float2(*(const __half2*)&g_Yh[2][base + (size_t)i*DD + d]);
        qs[i][d] = fq.x; qs[i][d+1] = fq.y;
        ks[i][d] = fk.x; ks[i][d+1] = fk.y;
        vs[i][d] = fv.x; vs[i][d+1] = fv.y;
    }
    if (tid < NSEQ) pv[tid] = g_P[((size_t)b*NSEQ + tid)*HH + h];
    __syncthreads();
    float al = alpha[0], bq = bqp[h];
    for (int idx = tid; idx < NSEQ*NSEQ; idx += 128) {
        int i = idx / NSEQ, j = idx - i * NSEQ;
        float s = 0.f;
        #pragma unroll
        for (int dv = 0; dv < 16; dv++) {
            float4 a = *(const float4*)&qs[i][dv*4];
            float4 c = *(const float4*)&ks[j][dv*4];
            s += a.x*c.x + a.y*c.y + a.z*c.z + a.w*c.w;
        }
        sc[i][j] = s * 0.125f
                 + rel[(i - j + NSEQ - 1) * HH + h]
                 + al * gsb[h * NSEQ*NSEQ + i * NSEQ + j]
                 + pv[i] - pv[j] + bq;
    }
    __syncthreads();
    if (tid < NSEQ) {
        float m = -1e30f;
        #pragma unroll
        for (int j = 0; j < NSEQ; j++) m = fmaxf(m, sc[tid][j]);
        float s = 0.f;
        #pragma unroll
        for (int j = 0; j < NSEQ; j++) { float e = __expf(sc[tid][j] - m); sc[tid][j] = e; s += e; }
        float inv = 1.f / s;
        #pragma unroll
        for (int j = 0; j < NSEQ; j++) sc[tid][j] *= inv;
    }
    __syncthreads();
    #pragma unroll
    for (int l = 0; l < 10; l++) {
        int idx = tid + l * 128;
        int i = idx >> 6, d = idx & 63;
        float o = 0.f;
        #pragma unroll
        for (int j = 0; j < NSEQ; j++) o += sc[i][j] * vs[j][d];
        g_AOh[base + (size_t)i*DD + d] = __float2half_rn(o);
    }
}

extern "C" void kernel_launch(void* const* d_in, const int* in_sizes, int n_in,
                              void* d_out, int out_size) {
    const float* x    = (const float*)d_in[0];
    const float* Wq   = (const float*)d_in[1];
    const float* Wk   = (const float*)d_in[2];
    const float* Wv   = (const float*)d_in[3];
    const float* gq_g = (const float*)d_in[4];
    const float* gq_b = (const float*)d_in[5];
    const float* gk_g = (const float*)d_in[6];
    const float* gk_b = (const float*)d_in[7];
    const float* gv_g = (const float*)d_in[8];
    const float* gv_b = (const float*)d_in[9];
    const float* rel  = (const float*)d_in[10];
    const float* gsb  = (const float*)d_in[11];
    const float* alpha= (const float*)d_in[12];
    const float* Wqf  = (const float*)d_in[13];
    const float* bqf  = (const float*)d_in[14];
    const float* Wqp  = (const float*)d_in[15];
    const float* bqp  = (const float*)d_in[16];
    const float* Wo   = (const float*)d_in[17];
    const float* bo   = (const float*)d_in[18];
    float* out = (float*)d_out;

    cudaFuncSetAttribute(k_conv_h, cudaFuncAttributeMaxDynamicSharedMemorySize, SMEM_DYN4);
    cudaFuncSetAttribute(k_out_h,  cudaFuncAttributeMaxDynamicSharedMemorySize, SMEM_DYN);

    k_prepXh<<<(MTOT*DD/4)/256, 256>>>(x);
    k_prepB<<<dim3(KC/256, DD, 3), 256>>>(Wq, Wk, Wv);
    k_prepMisc<<<(DD*DD + DQF*DD)/256, 256>>>(Wo, Wqf);
    k_qfp_tc<<<MTOT/128, 256>>>(bqf, Wqp);
    k_conv_h<<<dim3(DD/128, MTOT/128, 3), 256, SMEM_DYN4>>>(0);
    k_ln3<<<MTOT, 128>>>(gq_g, gq_b, gk_g, gk_b, gv_g, gv_b);
    k_attn<<<BB*HH, 128>>>(rel, gsb, alpha, bqp);
    k_out_h<<<dim3(DD/128, MTOT/128), 256, SMEM_DYN>>>(bo, out);
}